// round 8
// baseline (speedup 1.0000x reference)
#include <cuda_runtime.h>

// Apply 4x4 gate U to wires {5,13} of a 26-wire (dim-2) state vector.
// Target address bits: 20 (wire 5, MSB of t) and 12 (wire 13, LSB of t).
// REST = 2^24; each thread handles 4 consecutive rest indices (float4) on
// each of the 4 butterfly legs -> fully coalesced 16B accesses.
//
// R7 change vs R6(=R1): __ldcg on the state loads. L1D is flushed per
// launch and x has zero reuse, so every load misses L1 anyway; .cg skips
// L1 line allocation, trimming l1tex wavefront-queue work. L2/DRAM path
// unchanged (unlike .cs, which regressed).
// Measured baseline: 81.95us, ~6400 GB/s HBM, 75us device time vs 64us
// theoretical floor for the irreducible 512 MB of traffic.

#define REST_COUNT (1u << 24)

__global__ __launch_bounds__(256)
void unitary_gate_kernel(const float* __restrict__ x,
                         const float* __restrict__ U,
                         float* __restrict__ y)
{
    unsigned tid = blockIdx.x * blockDim.x + threadIdx.x;   // 0 .. 2^22-1
    unsigned r = tid << 2;                                  // rest index (x4)

    // Insert zero bits at positions 12 and 20.
    unsigned base = (r & 0xFFFu) | ((r & 0x7F000u) << 1) | ((r >> 19) << 21);

    const float4* __restrict__ x4 = (const float4*)x;
    float4* __restrict__ y4 = (float4*)y;

    unsigned i0 = base >> 2;                              // t=0
    unsigned i1 = (base + (1u << 12)) >> 2;               // t=1
    unsigned i2 = (base + (1u << 20)) >> 2;               // t=2
    unsigned i3 = (base + (1u << 20) + (1u << 12)) >> 2;  // t=3

    // L2-only loads: x is never reused and L1 is flushed per launch anyway.
    float4 a0 = __ldcg(&x4[i0]);
    float4 a1 = __ldcg(&x4[i1]);
    float4 a2 = __ldcg(&x4[i2]);
    float4 a3 = __ldcg(&x4[i3]);

    // U broadcasts via L1 (uniform across threads; the one reused input).
    float u[16];
#pragma unroll
    for (int k = 0; k < 16; ++k) u[k] = __ldg(U + k);

    float4 o0, o1, o2, o3;
    o0.x = u[0]*a0.x + u[1]*a1.x + u[2]*a2.x + u[3]*a3.x;
    o0.y = u[0]*a0.y + u[1]*a1.y + u[2]*a2.y + u[3]*a3.y;
    o0.z = u[0]*a0.z + u[1]*a1.z + u[2]*a2.z + u[3]*a3.z;
    o0.w = u[0]*a0.w + u[1]*a1.w + u[2]*a2.w + u[3]*a3.w;

    o1.x = u[4]*a0.x + u[5]*a1.x + u[6]*a2.x + u[7]*a3.x;
    o1.y = u[4]*a0.y + u[5]*a1.y + u[6]*a2.y + u[7]*a3.y;
    o1.z = u[4]*a0.z + u[5]*a1.z + u[6]*a2.z + u[7]*a3.z;
    o1.w = u[4]*a0.w + u[5]*a1.w + u[6]*a2.w + u[7]*a3.w;

    o2.x = u[8]*a0.x + u[9]*a1.x + u[10]*a2.x + u[11]*a3.x;
    o2.y = u[8]*a0.y + u[9]*a1.y + u[10]*a2.y + u[11]*a3.y;
    o2.z = u[8]*a0.z + u[9]*a1.z + u[10]*a2.z + u[11]*a3.z;
    o2.w = u[8]*a0.w + u[9]*a1.w + u[10]*a2.w + u[11]*a3.w;

    o3.x = u[12]*a0.x + u[13]*a1.x + u[14]*a2.x + u[15]*a3.x;
    o3.y = u[12]*a0.y + u[13]*a1.y + u[14]*a2.y + u[15]*a3.y;
    o3.z = u[12]*a0.z + u[13]*a1.z + u[14]*a2.z + u[15]*a3.z;
    o3.w = u[12]*a0.w + u[13]*a1.w + u[14]*a2.w + u[15]*a3.w;

    y4[i0] = o0;
    y4[i1] = o1;
    y4[i2] = o2;
    y4[i3] = o3;
}

extern "C" void kernel_launch(void* const* d_in, const int* in_sizes, int n_in,
                              void* d_out, int out_size)
{
    const float* x = (const float*)d_in[0];
    const float* U = (const float*)d_in[1];
    float* y = (float*)d_out;

    unsigned threads = 256;
    unsigned total_threads = REST_COUNT / 4;   // 2^22
    unsigned blocks = total_threads / threads; // 16384

    unitary_gate_kernel<<<blocks, threads>>>(x, U, y);
}

// round 9
// speedup vs baseline: 1.0012x; 1.0012x over previous
#include <cuda_runtime.h>

// FINAL: Apply 4x4 gate U to wires {5,13} of a 26-wire (dim-2) state vector.
// Target address bits: 20 (wire 5, MSB of t) and 12 (wire 13, LSB of t).
// REST = 2^24; each thread handles 4 consecutive rest indices (float4) on
// each of the 4 butterfly legs -> fully coalesced 16B accesses on all legs
// (leg strides 16KB/4MB apart, distinct 128B lines, no conflicts).
//
// Converged configuration after 8 measured rounds:
//  - __ldcg on state loads (x zero-reuse, L1 flushed per launch anyway):
//    best device profile measured (74.75us, DRAM 81.5%, 6453 GB/s).
//  - default-cached stores, U via __ldg (the one reused input).
//  - 256 threads, 1 float4-group/thread (occupancy/unroll/streaming-hint
//    levers all measured neutral-or-worse across R2-R4).
// Device time 74.75us vs 64us pure-spec floor for the irreducible 512 MB
// -> ~86% of spec, the realistic 50/50 read/write HBM3e ceiling.

#define REST_COUNT (1u << 24)

__global__ __launch_bounds__(256)
void unitary_gate_kernel(const float* __restrict__ x,
                         const float* __restrict__ U,
                         float* __restrict__ y)
{
    unsigned tid = blockIdx.x * blockDim.x + threadIdx.x;   // 0 .. 2^22-1
    unsigned r = tid << 2;                                  // rest index (x4)

    // Insert zero bits at positions 12 and 20.
    unsigned base = (r & 0xFFFu) | ((r & 0x7F000u) << 1) | ((r >> 19) << 21);

    const float4* __restrict__ x4 = (const float4*)x;
    float4* __restrict__ y4 = (float4*)y;

    unsigned i0 = base >> 2;                              // t=0
    unsigned i1 = (base + (1u << 12)) >> 2;               // t=1
    unsigned i2 = (base + (1u << 20)) >> 2;               // t=2
    unsigned i3 = (base + (1u << 20) + (1u << 12)) >> 2;  // t=3

    // L2-only loads: x is never reused and L1 is flushed per launch anyway.
    float4 a0 = __ldcg(&x4[i0]);
    float4 a1 = __ldcg(&x4[i1]);
    float4 a2 = __ldcg(&x4[i2]);
    float4 a3 = __ldcg(&x4[i3]);

    // U broadcasts via L1 (uniform across threads; the one reused input).
    float u[16];
#pragma unroll
    for (int k = 0; k < 16; ++k) u[k] = __ldg(U + k);

    float4 o0, o1, o2, o3;
    o0.x = u[0]*a0.x + u[1]*a1.x + u[2]*a2.x + u[3]*a3.x;
    o0.y = u[0]*a0.y + u[1]*a1.y + u[2]*a2.y + u[3]*a3.y;
    o0.z = u[0]*a0.z + u[1]*a1.z + u[2]*a2.z + u[3]*a3.z;
    o0.w = u[0]*a0.w + u[1]*a1.w + u[2]*a2.w + u[3]*a3.w;

    o1.x = u[4]*a0.x + u[5]*a1.x + u[6]*a2.x + u[7]*a3.x;
    o1.y = u[4]*a0.y + u[5]*a1.y + u[6]*a2.y + u[7]*a3.y;
    o1.z = u[4]*a0.z + u[5]*a1.z + u[6]*a2.z + u[7]*a3.z;
    o1.w = u[4]*a0.w + u[5]*a1.w + u[6]*a2.w + u[7]*a3.w;

    o2.x = u[8]*a0.x + u[9]*a1.x + u[10]*a2.x + u[11]*a3.x;
    o2.y = u[8]*a0.y + u[9]*a1.y + u[10]*a2.y + u[11]*a3.y;
    o2.z = u[8]*a0.z + u[9]*a1.z + u[10]*a2.z + u[11]*a3.z;
    o2.w = u[8]*a0.w + u[9]*a1.w + u[10]*a2.w + u[11]*a3.w;

    o3.x = u[12]*a0.x + u[13]*a1.x + u[14]*a2.x + u[15]*a3.x;
    o3.y = u[12]*a0.y + u[13]*a1.y + u[14]*a2.y + u[15]*a3.y;
    o3.z = u[12]*a0.z + u[13]*a1.z + u[14]*a2.z + u[15]*a3.z;
    o3.w = u[12]*a0.w + u[13]*a1.w + u[14]*a2.w + u[15]*a3.w;

    y4[i0] = o0;
    y4[i1] = o1;
    y4[i2] = o2;
    y4[i3] = o3;
}

extern "C" void kernel_launch(void* const* d_in, const int* in_sizes, int n_in,
                              void* d_out, int out_size)
{
    const float* x = (const float*)d_in[0];
    const float* U = (const float*)d_in[1];
    float* y = (float*)d_out;

    unsigned threads = 256;
    unsigned total_threads = REST_COUNT / 4;   // 2^22
    unsigned blocks = total_threads / threads; // 16384

    unitary_gate_kernel<<<blocks, threads>>>(x, U, y);
}